// round 16
// baseline (speedup 1.0000x reference)
#include <cuda_runtime.h>
#include <math.h>
#include <stdint.h>

// Problem constants
#define HH 128
#define WW 128
#define BATCH 2
#define CFEAT 128
#define PLANE (HH * WW)
#define KDIM (9 * CFEAT)          // 1152

// ---------------------------------------------------------------------------
// cp.async / ldmatrix / mma.sync primitives (sm_80-era, valid on sm_100)
// ---------------------------------------------------------------------------
__device__ __forceinline__ void cp16s(uint32_t smem, const void* gmem) {
    asm volatile("cp.async.cg.shared.global [%0], [%1], 16;" :: "r"(smem), "l"(gmem));
}
__device__ __forceinline__ void cp16z(uint32_t smem, const void* gmem, uint32_t n) {
    asm volatile("cp.async.cg.shared.global [%0], [%1], 16, %2;"
                 :: "r"(smem), "l"(gmem), "r"(n));
}
#define CP_COMMIT() asm volatile("cp.async.commit_group;")
template <int N>
__device__ __forceinline__ void cp_wait() {
    asm volatile("cp.async.wait_group %0;" :: "n"(N));
}

#define LDMX4(r, addr) \
    asm volatile("ldmatrix.sync.aligned.m8n8.x4.shared.b16 {%0,%1,%2,%3}, [%4];" \
                 : "=r"((r)[0]), "=r"((r)[1]), "=r"((r)[2]), "=r"((r)[3]) \
                 : "r"(addr))

__device__ __forceinline__ void mma_tf32_16n8k8(float* c, const uint32_t* a,
                                                uint32_t b0, uint32_t b1) {
    asm volatile(
        "mma.sync.aligned.m16n8k8.row.col.f32.tf32.tf32.f32 "
        "{%0,%1,%2,%3}, {%4,%5,%6,%7}, {%8,%9}, {%0,%1,%2,%3};"
        : "+f"(c[0]), "+f"(c[1]), "+f"(c[2]), "+f"(c[3])
        : "r"(a[0]), "r"(a[1]), "r"(a[2]), "r"(a[3]), "r"(b0), "r"(b1));
}

__device__ __forceinline__ float to_tf32(float x) {
    uint32_t u;
    asm("cvt.rna.tf32.f32 %0, %1;" : "=r"(u) : "f"(x));
    return __uint_as_float(u);
}

// ---------------------------------------------------------------------------
// Scratch (device globals; zero-initialized; no allocation allowed)
// ---------------------------------------------------------------------------
#define CPAD1 160
__device__ float g_tmp1T[BATCH * PLANE * 64];      // conv1 out [b][px][64] tf32
__device__ float g_off  [BATCH * 18 * PLANE];      // offsets NCHW
__device__ float g_tmp2T[BATCH * PLANE * CFEAT];   // deform out [b][px][o] tf32
__device__ float g_tmp3T[BATCH * PLANE * 64];      // fh conv1 out [b][px][64] tf32
__device__ float g_dwt2 [CFEAT * KDIM];            // dweight [o][k*128+c] tf32
__device__ float g_wc1  [9 * 64 * CPAD1];          // off_w1 [tap][o][c_pad] tf32
__device__ float g_wc3  [9 * 64 * CFEAT];          // fh_w1  [tap][o][c] tf32
__device__ float g_wc2  [9 * 32 * 64];             // off_w2 [tap][o32][c] tf32 (pad 0)
__device__ float g_wc4  [9 * 32 * 64];             // fh_w2  [tap][o32][c] tf32 (pad 0)
__device__ float g_inT1 [BATCH * PLANE * CPAD1];   // concat(feat,flow)T tf32

// ---------------------------------------------------------------------------
// Merged weight prep
// ---------------------------------------------------------------------------
#define WP_N1 (CFEAT * KDIM)
#define WP_N2 (64 * 130 * 9)
#define WP_N3 (64 * 128 * 9)
#define WP_N4 (18 * 64 * 9)
#define WP_N5 (2 * 64 * 9)
#define WP_TOTAL (WP_N1 + WP_N2 + WP_N3 + WP_N4 + WP_N5)

__global__ void wprep_kernel(const float* __restrict__ dw,
                             const float* __restrict__ ow1,
                             const float* __restrict__ fw1,
                             const float* __restrict__ ow2,
                             const float* __restrict__ fw2) {
    int t = blockIdx.x * blockDim.x + threadIdx.x;
    if (t < WP_N1) {
        int o  = t / KDIM;
        int r  = t % KDIM;
        int c  = r / 9;
        int kk = r % 9;
        g_dwt2[(size_t)o * KDIM + kk * 128 + c] = to_tf32(dw[t]);
        return;
    }
    t -= WP_N1;
    if (t < WP_N2) {
        int o  = t / (130 * 9);
        int r  = t % (130 * 9);
        int c  = r / 9;
        int kk = r % 9;
        g_wc1[(kk * 64 + o) * CPAD1 + c] = to_tf32(ow1[t]);
        return;
    }
    t -= WP_N2;
    if (t < WP_N3) {
        int o  = t / (128 * 9);
        int r  = t % (128 * 9);
        int c  = r / 9;
        int kk = r % 9;
        g_wc3[(kk * 64 + o) * CFEAT + c] = to_tf32(fw1[t]);
        return;
    }
    t -= WP_N3;
    if (t < WP_N4) {
        int o  = t / (64 * 9);
        int r  = t % (64 * 9);
        int c  = r / 9;
        int kk = r % 9;
        g_wc2[(kk * 32 + o) * 64 + c] = to_tf32(ow2[t]);
        return;
    }
    t -= WP_N4;
    if (t < WP_N5) {
        int o  = t / (64 * 9);
        int r  = t % (64 * 9);
        int c  = r / 9;
        int kk = r % 9;
        g_wc4[(kk * 32 + o) * 64 + c] = to_tf32(fw2[t]);
    }
}

// ---------------------------------------------------------------------------
// catT: concat(feat[128], flow[2]) NCHW -> g_inT1[b][px][160] (tf32, zero pad)
// ---------------------------------------------------------------------------
__global__ __launch_bounds__(256)
void catT_kernel(const float* __restrict__ feat, const float* __restrict__ flow) {
    __shared__ float s[64][164];
    const int tid = threadIdx.x;
    const int pxt = tid & 63;
    const int cg  = tid >> 6;
    const int b   = blockIdx.z;
    const int px0 = blockIdx.x * 64;
    const int px  = px0 + pxt;

#pragma unroll 8
    for (int j = 0; j < 40; j++) {
        int c = cg * 40 + j;
        float v = 0.f;
        if (c < 128)      v = feat[(size_t)(b * 128 + c) * PLANE + px];
        else if (c < 130) v = flow[(size_t)(b * 2 + (c - 128)) * PLANE + px];
        s[pxt][c] = to_tf32(v);
    }
    __syncthreads();

    const int r = tid >> 2;
    const int q = tid & 3;
    float* dst = g_inT1 + (size_t)(b * PLANE + px0 + r) * CPAD1 + q * 40;
    const float* src = &s[r][q * 40];
#pragma unroll
    for (int i = 0; i < 10; i++)
        ((float4*)dst)[i] = ((const float4*)src)[i];
}

// ---------------------------------------------------------------------------
// conv3x3 via mma.sync tf32 — v2 split tile: CTA = 64 px x 64 o.
// grid = (2*HH, 1, B): h = bx>>1, pxh = (bx&1)*64.
// 8 warps: wm = wid&1 (32-px half), wn = wid>>1 (16-o quarter).
// smem = 2*(64+64)*36*4 = 36864 B -> high residency.
// ---------------------------------------------------------------------------
#define CAP 36
#define CV_AF (64 * CAP)
#define CV_BF (64 * CAP)
#define CONV_SMEM (2 * (CV_AF + CV_BF) * 4)   // 36864 B

template <int CPAD, bool RELU>
__global__ __launch_bounds__(256)
void conv_mma_kernel(const float* __restrict__ inT, const float* __restrict__ wt,
                     const float* __restrict__ bias, float* __restrict__ outT) {
    constexpr int CPC = CPAD / 32;
    constexpr int NCH = 9 * CPC;

    extern __shared__ float dsm[];
    const uint32_t sb = (uint32_t)__cvta_generic_to_shared(dsm);
    const uint32_t As_a[2] = {sb, sb + (CV_AF + CV_BF) * 4};
    const uint32_t Bs_a[2] = {sb + CV_AF * 4, sb + (2 * CV_AF + CV_BF) * 4};

    const int tid = threadIdx.x;
    const int lid = tid & 31;
    const int wid = tid >> 5;
    const int h   = blockIdx.x >> 1;
    const int pxh = (blockIdx.x & 1) * 64;
    const int b   = blockIdx.z;

    auto load_chunk = [&](int lch, int buf) {
        const int tap = lch / CPC;
        const int c0  = (lch % CPC) * 32;
        const int dh  = tap / 3 - 1;
        const int dw  = tap % 3 - 1;
        const int h2  = h + dh;
        const bool vh = (h2 >= 0) && (h2 < HH);
        const int h2c = vh ? h2 : 0;
        const float* inrow = inT + (size_t)(b * PLANE + h2c * WW) * CPAD;
        // A: 512 segs (64 rows x 8), 2/thread
#pragma unroll
        for (int i = 0; i < 2; i++) {
            int seg = tid * 2 + i;
            int row = seg >> 3;
            int s8  = seg & 7;
            int ws  = pxh + row + dw;
            bool v  = vh && (ws >= 0) && (ws < WW);
            int wsc = v ? ws : 0;
            cp16z(As_a[buf] + (uint32_t)(row * CAP + s8 * 4) * 4,
                  inrow + (size_t)wsc * CPAD + c0 + s8 * 4, v ? 16u : 0u);
        }
        // B: 512 segs (64 o x 8), 2/thread
#pragma unroll
        for (int i = 0; i < 2; i++) {
            int seg = tid * 2 + i;
            int o   = seg >> 3;
            int s8  = seg & 7;
            cp16s(Bs_a[buf] + (uint32_t)(o * CAP + s8 * 4) * 4,
                  wt + (size_t)(tap * 64 + o) * CPAD + c0 + s8 * 4);
        }
        CP_COMMIT();
    };

    const int wm = wid & 1;       // 32-px half of the 64-px tile
    const int wn = wid >> 1;      // 16-o quarter
    const int j = lid >> 3, i8 = lid & 7;
    const uint32_t aoff = (uint32_t)(((j & 1) * 8 + i8) * CAP + (j >> 1) * 4) * 4;
    const uint32_t boff = (uint32_t)(((j >> 1) * 8 + i8) * CAP + (j & 1) * 4) * 4;

    float c[2][2][4];
#pragma unroll
    for (int mt = 0; mt < 2; mt++)
#pragma unroll
        for (int nt = 0; nt < 2; nt++)
#pragma unroll
            for (int e = 0; e < 4; e++) c[mt][nt][e] = 0.f;

    load_chunk(0, 0);

    for (int ch = 0; ch < NCH; ch++) {
        const int cur = ch & 1;
        if (ch + 1 < NCH) {
            load_chunk(ch + 1, cur ^ 1);
            cp_wait<1>();
        } else {
            cp_wait<0>();
        }
        __syncthreads();

#pragma unroll
        for (int ks = 0; ks < 4; ks++) {
            const uint32_t kk4 = (uint32_t)(ks * 8) * 4;
            uint32_t a[2][4];
#pragma unroll
            for (int mt = 0; mt < 2; mt++)
                LDMX4(a[mt], As_a[cur] + (uint32_t)((wm * 32 + mt * 16) * CAP) * 4
                             + kk4 + aoff);
            uint32_t bf[4];
            LDMX4(bf, Bs_a[cur] + (uint32_t)((wn * 16) * CAP) * 4 + kk4 + boff);
#pragma unroll
            for (int mt = 0; mt < 2; mt++)
#pragma unroll
                for (int nt = 0; nt < 2; nt++)
                    mma_tf32_16n8k8(c[mt][nt], a[mt], bf[nt * 2], bf[nt * 2 + 1]);
        }
        __syncthreads();
    }

    // Epilogue: frags (+bias, relu, tf32) -> smem [px][o] (stride 68) -> outT
    float* s_t = dsm;
#pragma unroll
    for (int mt = 0; mt < 2; mt++)
#pragma unroll
        for (int nt = 0; nt < 2; nt++) {
            int px = wm * 32 + mt * 16 + (lid >> 2);
            int o  = wn * 16 + nt * 8 + (lid & 3) * 2;
            float b0 = __ldg(&bias[o]);
            float b1 = __ldg(&bias[o + 1]);
            float v0 = c[mt][nt][0] + b0;
            float v1 = c[mt][nt][1] + b1;
            float v2 = c[mt][nt][2] + b0;
            float v3 = c[mt][nt][3] + b1;
            if (RELU) {
                v0 = fmaxf(v0, 0.f); v1 = fmaxf(v1, 0.f);
                v2 = fmaxf(v2, 0.f); v3 = fmaxf(v3, 0.f);
            }
            s_t[px * 68 + o]           = to_tf32(v0);
            s_t[px * 68 + o + 1]       = to_tf32(v1);
            s_t[(px + 8) * 68 + o]     = to_tf32(v2);
            s_t[(px + 8) * 68 + o + 1] = to_tf32(v3);
        }
    __syncthreads();
    {
        // 64 rows of 64 floats: 4 threads per row, 16 floats each
        const int px = tid >> 2;
        const int q  = tid & 3;
        float* dst = outT + (size_t)(b * PLANE + h * WW + pxh + px) * 64 + q * 16;
        const float* src = s_t + px * 68 + q * 16;
#pragma unroll
        for (int i = 0; i < 4; i++)
            ((float4*)dst)[i] = ((const float4*)src)[i];
    }
}

// ---------------------------------------------------------------------------
// Small conv3x3 via mma (round-14 proven). grid = (HH, 1, B).
// ---------------------------------------------------------------------------
#define SC_AF (128 * CAP)
#define SC_BF (32 * CAP)
#define SC_SMEM (2 * (SC_AF + SC_BF) * 4)   // 46080 B

template <int COUT, bool RES>
__global__ __launch_bounds__(256)
void conv_mma_small_kernel(const float* __restrict__ inT, const float* __restrict__ wsm,
                           const float* __restrict__ bias, const float* __restrict__ res,
                           float* __restrict__ out) {
    constexpr int NCH = 18;

    extern __shared__ float dsm[];
    const uint32_t sb = (uint32_t)__cvta_generic_to_shared(dsm);
    const uint32_t As_a[2] = {sb, sb + (SC_AF + SC_BF) * 4};
    const uint32_t Bs_a[2] = {sb + SC_AF * 4, sb + (2 * SC_AF + SC_BF) * 4};

    const int tid = threadIdx.x;
    const int lid = tid & 31;
    const int wid = tid >> 5;
    const int h   = blockIdx.x;
    const int b   = blockIdx.z;

    auto load_chunk = [&](int lch, int buf) {
        const int tap = lch >> 1;
        const int c0  = (lch & 1) * 32;
        const int dh  = tap / 3 - 1;
        const int dw  = tap % 3 - 1;
        const int h2  = h + dh;
        const bool vh = (h2 >= 0) && (h2 < HH);
        const int h2c = vh ? h2 : 0;
        const float* inrow = inT + (size_t)(b * PLANE + h2c * WW) * 64;
#pragma unroll
        for (int i = 0; i < 4; i++) {
            int seg = tid * 4 + i;
            int row = seg >> 3;
            int s8  = seg & 7;
            int ws  = row + dw;
            bool v  = vh && (ws >= 0) && (ws < WW);
            int wsc = v ? ws : 0;
            cp16z(As_a[buf] + (uint32_t)(row * CAP + s8 * 4) * 4,
                  inrow + (size_t)wsc * 64 + c0 + s8 * 4, v ? 16u : 0u);
        }
        {
            int o  = tid >> 3;
            int s8 = tid & 7;
            cp16s(Bs_a[buf] + (uint32_t)(o * CAP + s8 * 4) * 4,
                  wsm + (size_t)(tap * 32 + o) * 64 + c0 + s8 * 4);
        }
        CP_COMMIT();
    };

    const int j = lid >> 3, i8 = lid & 7;
    const uint32_t aoff = (uint32_t)(((j & 1) * 8 + i8) * CAP + (j >> 1) * 4) * 4;
    const uint32_t boff = (uint32_t)(((j >> 1) * 8 + i8) * CAP + (j & 1) * 4) * 4;

    float c[4][4];
#pragma unroll
    for (int nt = 0; nt < 4; nt++)
#pragma unroll
        for (int e = 0; e < 4; e++) c[nt][e] = 0.f;

    load_chunk(0, 0);

    for (int ch = 0; ch < NCH; ch++) {
        const int cur = ch & 1;
        if (ch + 1 < NCH) {
            load_chunk(ch + 1, cur ^ 1);
            cp_wait<1>();
        } else {
            cp_wait<0>();
        }
        __syncthreads();

#pragma unroll
        for (int ks = 0; ks < 4; ks++) {
            const uint32_t kk4 = (uint32_t)(ks * 8) * 4;
            uint32_t a[4];
            LDMX4(a, As_a[cur] + (uint32_t)((wid * 16) * CAP) * 4 + kk4 + aoff);
            uint32_t bf[2][4];
#pragma unroll
            for (int g = 0; g < 2; g++)
                LDMX4(bf[g], Bs_a[cur] + (uint32_t)((g * 16) * CAP) * 4 + kk4 + boff);
#pragma unroll
            for (int nt = 0; nt < 4; nt++)
                mma_tf32_16n8k8(c[nt], a,
                                bf[nt >> 1][(nt & 1) * 2],
                                bf[nt >> 1][(nt & 1) * 2 + 1]);
        }
        __syncthreads();
    }

    float* s_t = dsm;
#pragma unroll
    for (int nt = 0; nt < 4; nt++) {
        int px = wid * 16 + (lid >> 2);
        int o  = nt * 8 + (lid & 3) * 2;
        s_t[px * 34 + o]           = c[nt][0];
        s_t[px * 34 + o + 1]       = c[nt][1];
        s_t[(px + 8) * 34 + o]     = c[nt][2];
        s_t[(px + 8) * 34 + o + 1] = c[nt][3];
    }
    __syncthreads();
    for (int idx = tid; idx < COUT * 128; idx += 256) {
        int o  = idx >> 7;
        int px = idx & 127;
        float v = s_t[px * 34 + o] + __ldg(&bias[o]);
        size_t gi = (size_t)(b * COUT + o) * PLANE + h * WW + px;
        if (RES) v += res[gi];
        out[gi] = v;
    }
}

// ---------------------------------------------------------------------------
// FUSED deform GEMM (round-13 proven). grid = (128, 1, B).
// ---------------------------------------------------------------------------
#define AP 36
#define TILE_F (128 * AP)
#define FD_SMEM ((4608 * 2 + 4 * TILE_F) * 4)       // 110592 B

__global__ __launch_bounds__(256)
void dgemm_fused_kernel(const float* __restrict__ feat, const float* __restrict__ offs,
                        const float* __restrict__ dbias) {
    constexpr int NCH = KDIM / 32;

    extern __shared__ float dsm[];
    int*   s_idx = (int*)dsm;
    float* s_wt  = dsm + 4608;
    float* A_f[2] = {dsm + 9216,  dsm + 9216 + TILE_F};
    const uint32_t sb = (uint32_t)__cvta_generic_to_shared(dsm);
    const uint32_t Bs_a[2] = {sb + (9216 + 2 * TILE_F) * 4,
                              sb + (9216 + 3 * TILE_F) * 4};
    const uint32_t As_a[2] = {sb + 9216 * 4, sb + (9216 + TILE_F) * 4};

    const int tid = threadIdx.x;
    const int lid = tid & 31;
    const int wid = tid >> 5;
    const int px0 = blockIdx.x * 128;
    const int b   = blockIdx.z;

    auto load_B = [&](int ch, int buf) {
        const int kc0 = (ch >> 2) * 128 + (ch & 3) * 32;
#pragma unroll
        for (int i = 0; i < 4; i++) {
            int seg = tid * 4 + i;
            int o   = seg >> 3;
            int s   = seg & 7;
            cp16s(Bs_a[buf] + (uint32_t)(o * AP + s * 4) * 4,
                  g_dwt2 + (size_t)o * KDIM + kc0 + s * 4);
        }
        CP_COMMIT();
    };

    load_B(0, 0);

    for (int t = tid; t < 1152; t += 256) {
        int px = t / 9;
        int k  = t % 9;
        int g  = px0 + px;
        int h  = g >> 7;
        int w  = g & 127;
        float offy = offs[(size_t)(b * 18 + 2 * k)     * PLANE + g];
        float offx = offs[(size_t)(b * 18 + 2 * k + 1) * PLANE + g];
        float fy = (float)(h + k / 3 - 1) + offy;
        float fx = (float)(w + k % 3 - 1) + offx;
        float y0f = floorf(fy), x0f = floorf(fx);
        float ly = fy - y0f, lx = fx - x0f;
        int y0 = (int)y0f, x0 = (int)x0f;
        float q[4] = {(1.f - ly) * (1.f - lx), (1.f - ly) * lx,
                      ly * (1.f - lx),          ly * lx};
        int ys[4] = {y0, y0, y0 + 1, y0 + 1};
        int xs[4] = {x0, x0 + 1, x0, x0 + 1};
#pragma unroll
        for (int c4 = 0; c4 < 4; c4++) {
            bool valid = (ys[c4] >= 0) && (ys[c4] < HH) && (xs[c4] >= 0) && (xs[c4] < WW);
            s_idx[t * 4 + c4] = valid ? (ys[c4] * WW + xs[c4]) : 0;
            s_wt [t * 4 + c4] = valid ? q[c4] : 0.f;
        }
    }
    __syncthreads();

    const int gpx = tid & 127;
    const int gcg = tid >> 7;
    auto gather_A = [&](int ch, int buf) {
        const int k  = ch >> 2;
        const int c0 = (ch & 3) * 32 + gcg * 16;
        const int4   iv = *(const int4*)&s_idx[(gpx * 9 + k) * 4];
        const float4 qv = *(const float4*)&s_wt[(gpx * 9 + k) * 4];
        const float* fb = feat + (size_t)b * CFEAT * PLANE;
        float* arow = A_f[buf] + gpx * AP + gcg * 16;
#pragma unroll
        for (int j = 0; j < 16; j++) {
            const float* fc = fb + (size_t)(c0 + j) * PLANE;
            arow[j] = to_tf32(qv.x * fc[iv.x] + qv.y * fc[iv.y]
                            + qv.z * fc[iv.z] + qv.w * fc[iv.w]);
        }
    };

    gather_A(0, 0);

    const int wpx = wid & 1;
    const int wo  = wid >> 1;
    const int j = lid >> 3, i8 = lid & 7;
    const uint32_t aoff = (uint32_t)(((j & 1) * 8 + i8) * AP + (j >> 1) * 4) * 4;
    const uint32_t boff = (uint32_t)(((j >> 1) * 8 + i8) * AP + (j & 1) * 4) * 4;

    float c[4][4][4];
#pragma unroll
    for (int mt = 0; mt < 4; mt++)
#pragma unroll
        for (int nt = 0; nt < 4; nt++)
#pragma unroll
            for (int e = 0; e < 4; e++) c[mt][nt][e] = 0.f;

    for (int ch = 0; ch < NCH; ch++) {
        const int cur = ch & 1;
        if (ch + 1 < NCH) {
            load_B(ch + 1, cur ^ 1);
            cp_wait<1>();
        } else {
            cp_wait<0>();
        }
        __syncthreads();

#pragma unroll
        for (int ks = 0; ks < 4; ks++) {
            const uint32_t kk4 = (uint32_t)(ks * 8) * 4;
            uint32_t a[4][4];
#pragma unroll
            for (int mt = 0; mt < 4; mt++)
                LDMX4(a[mt], As_a[cur] + (uint32_t)((wpx * 64 + mt * 16) * AP) * 4
                             + kk4 + aoff);
            uint32_t bf[2][4];
#pragma unroll
            for (int g = 0; g < 2; g++)
                LDMX4(bf[g], Bs_a[cur] + (uint32_t)((wo * 32 + g * 16) * AP) * 4
                             + kk4 + boff);
#pragma unroll
            for (int mt = 0; mt < 4; mt++)
#pragma unroll
                for (int nt = 0; nt < 4; nt++)
                    mma_tf32_16n8k8(c[mt][nt], a[mt],
                                    bf[nt >> 1][(nt & 1) * 2],
                                    bf[nt >> 1][(nt & 1) * 2 + 1]);
        }
        __syncthreads();
        if (ch + 1 < NCH) gather_A(ch + 1, cur ^ 1);
    }

    float* s_t = dsm;
#pragma unroll
    for (int mt = 0; mt < 4; mt++)
#pragma unroll
        for (int nt = 0; nt < 4; nt++) {
            int pxb = wpx * 64 + mt * 16 + (lid >> 2);
            int ob  = wo * 32 + nt * 8 + (lid & 3) * 2;
            float b0 = __ldg(&dbias[ob]);
            float b1 = __ldg(&dbias[ob + 1]);
            s_t[pxb * 132 + ob]           = to_tf32(c[mt][nt][0] + b0);
            s_t[pxb * 132 + ob + 1]       = to_tf32(c[mt][nt][1] + b1);
            s_t[(pxb + 8) * 132 + ob]     = to_tf32(c[mt][nt][2] + b0);
            s_t[(pxb + 8) * 132 + ob + 1] = to_tf32(c[mt][nt][3] + b1);
        }
    __syncthreads();
    {
        const int px = tid >> 1;
        const int hf = tid & 1;
        float* dst = g_tmp2T + (size_t)(b * PLANE + px0 + px) * CFEAT + hf * 64;
        const float* src = s_t + px * 132 + hf * 64;
#pragma unroll
        for (int i = 0; i < 16; i++)
            ((float4*)dst)[i] = ((const float4*)src)[i];
    }
}

// ---------------------------------------------------------------------------
// Launch
// ---------------------------------------------------------------------------
extern "C" void kernel_launch(void* const* d_in, const int* in_sizes, int n_in,
                              void* d_out, int out_size) {
    const float* feat    = (const float*)d_in[0];
    const float* flow    = (const float*)d_in[1];
    const float* off_w1  = (const float*)d_in[2];
    const float* off_b1  = (const float*)d_in[3];
    const float* off_w2  = (const float*)d_in[4];
    const float* off_b2  = (const float*)d_in[5];
    const float* dweight = (const float*)d_in[6];
    const float* dbias   = (const float*)d_in[7];
    const float* fh_w1   = (const float*)d_in[8];
    const float* fh_b1   = (const float*)d_in[9];
    const float* fh_w2   = (const float*)d_in[10];
    const float* fh_b2   = (const float*)d_in[11];
    float* out = (float*)d_out;

    float *tmp1T, *off, *tmp2T, *tmp3T, *wc1, *wc3, *wc2, *wc4, *inT1;
    cudaGetSymbolAddress((void**)&tmp1T, g_tmp1T);
    cudaGetSymbolAddress((void**)&off,   g_off);
    cudaGetSymbolAddress((void**)&tmp2T, g_tmp2T);
    cudaGetSymbolAddress((void**)&tmp3T, g_tmp3T);
    cudaGetSymbolAddress((void**)&wc1,   g_wc1);
    cudaGetSymbolAddress((void**)&wc3,   g_wc3);
    cudaGetSymbolAddress((void**)&wc2,   g_wc2);
    cudaGetSymbolAddress((void**)&wc4,   g_wc4);
    cudaGetSymbolAddress((void**)&inT1,  g_inT1);

    cudaFuncSetAttribute(dgemm_fused_kernel,
                         cudaFuncAttributeMaxDynamicSharedMemorySize, FD_SMEM);
    cudaFuncSetAttribute(conv_mma_kernel<CPAD1, true>,
                         cudaFuncAttributeMaxDynamicSharedMemorySize, CONV_SMEM);
    cudaFuncSetAttribute(conv_mma_kernel<CFEAT, true>,
                         cudaFuncAttributeMaxDynamicSharedMemorySize, CONV_SMEM);
    cudaFuncSetAttribute(conv_mma_small_kernel<18, false>,
                         cudaFuncAttributeMaxDynamicSharedMemorySize, SC_SMEM);
    cudaFuncSetAttribute(conv_mma_small_kernel<2, true>,
                         cudaFuncAttributeMaxDynamicSharedMemorySize, SC_SMEM);

    // 0. all weight transposes (one launch)
    wprep_kernel<<<(WP_TOTAL + 255) / 256, 256>>>(dweight, off_w1, fh_w1,
                                                  off_w2, fh_w2);

    // 1a. transpose concat(feat, flow) -> inT1 [px][160]
    catT_kernel<<<dim3(PLANE / 64, 1, BATCH), 256>>>(feat, flow);

    // 1b. conv1 via mma (split tile): 130 -> 64, relu -> tmp1T
    conv_mma_kernel<CPAD1, true><<<dim3(2 * HH, 1, BATCH), 256, CONV_SMEM>>>(
        inT1, wc1, off_b1, tmp1T);

    // 2. conv2 via mma: 64 -> 18 -> offsets NCHW
    conv_mma_small_kernel<18, false><<<dim3(HH, 1, BATCH), 256, SC_SMEM>>>(
        tmp1T, wc2, off_b2, nullptr, off);

    // 3. FUSED gather + deform GEMM -> tmp2T [px][o] (tf32, +bias)
    dgemm_fused_kernel<<<dim3(128, 1, BATCH), 256, FD_SMEM>>>(feat, off, dbias);

    // 4. fh conv1 via mma (split tile): 128 -> 64, relu -> tmp3T
    conv_mma_kernel<CFEAT, true><<<dim3(2 * HH, 1, BATCH), 256, CONV_SMEM>>>(
        tmp2T, wc3, fh_b1, tmp3T);

    // 5. fh conv2 via mma: 64 -> 2, + flow residual -> out NCHW
    conv_mma_small_kernel<2, true><<<dim3(HH, 1, BATCH), 256, SC_SMEM>>>(
        tmp3T, wc4, fh_b2, flow, out);
}

// round 17
// speedup vs baseline: 1.0040x; 1.0040x over previous
#include <cuda_runtime.h>
#include <math.h>
#include <stdint.h>

// Problem constants
#define HH 128
#define WW 128
#define BATCH 2
#define CFEAT 128
#define PLANE (HH * WW)
#define KDIM (9 * CFEAT)          // 1152

// ---------------------------------------------------------------------------
// cp.async / ldmatrix / mma.sync primitives (sm_80-era, valid on sm_100)
// ---------------------------------------------------------------------------
__device__ __forceinline__ void cp16s(uint32_t smem, const void* gmem) {
    asm volatile("cp.async.cg.shared.global [%0], [%1], 16;" :: "r"(smem), "l"(gmem));
}
__device__ __forceinline__ void cp16z(uint32_t smem, const void* gmem, uint32_t n) {
    asm volatile("cp.async.cg.shared.global [%0], [%1], 16, %2;"
                 :: "r"(smem), "l"(gmem), "r"(n));
}
#define CP_COMMIT() asm volatile("cp.async.commit_group;")
template <int N>
__device__ __forceinline__ void cp_wait() {
    asm volatile("cp.async.wait_group %0;" :: "n"(N));
}

#define LDMX4(r, addr) \
    asm volatile("ldmatrix.sync.aligned.m8n8.x4.shared.b16 {%0,%1,%2,%3}, [%4];" \
                 : "=r"((r)[0]), "=r"((r)[1]), "=r"((r)[2]), "=r"((r)[3]) \
                 : "r"(addr))

__device__ __forceinline__ void mma_tf32_16n8k8(float* c, const uint32_t* a,
                                                uint32_t b0, uint32_t b1) {
    asm volatile(
        "mma.sync.aligned.m16n8k8.row.col.f32.tf32.tf32.f32 "
        "{%0,%1,%2,%3}, {%4,%5,%6,%7}, {%8,%9}, {%0,%1,%2,%3};"
        : "+f"(c[0]), "+f"(c[1]), "+f"(c[2]), "+f"(c[3])
        : "r"(a[0]), "r"(a[1]), "r"(a[2]), "r"(a[3]), "r"(b0), "r"(b1));
}

__device__ __forceinline__ float to_tf32(float x) {
    uint32_t u;
    asm("cvt.rna.tf32.f32 %0, %1;" : "=r"(u) : "f"(x));
    return __uint_as_float(u);
}

// ---------------------------------------------------------------------------
// Scratch (device globals; zero-initialized; no allocation allowed)
// ---------------------------------------------------------------------------
#define CPAD1 160
__device__ float g_tmp1T[BATCH * PLANE * 64];      // conv1 out [b][px][64] tf32
__device__ float g_off  [BATCH * 18 * PLANE];      // offsets NCHW
__device__ float g_tmp2T[BATCH * PLANE * CFEAT];   // deform out [b][px][o] tf32
__device__ float g_tmp3T[BATCH * PLANE * 64];      // fh conv1 out [b][px][64] tf32
__device__ float g_dwt2 [CFEAT * KDIM];            // dweight [o][k*128+c] tf32
__device__ float g_wc1  [9 * 64 * CPAD1];          // off_w1 [tap][o][c_pad] tf32
__device__ float g_wc3  [9 * 64 * CFEAT];          // fh_w1  [tap][o][c] tf32
__device__ float g_wc2  [9 * 32 * 64];             // off_w2 [tap][o32][c] tf32 (pad 0)
__device__ float g_wc4  [9 * 32 * 64];             // fh_w2  [tap][o32][c] tf32 (pad 0)
__device__ float g_inT1 [BATCH * PLANE * CPAD1];   // concat(feat,flow)T tf32

// ---------------------------------------------------------------------------
// Merged weight prep
// ---------------------------------------------------------------------------
#define WP_N1 (CFEAT * KDIM)
#define WP_N2 (64 * 130 * 9)
#define WP_N3 (64 * 128 * 9)
#define WP_N4 (18 * 64 * 9)
#define WP_N5 (2 * 64 * 9)
#define WP_TOTAL (WP_N1 + WP_N2 + WP_N3 + WP_N4 + WP_N5)

__global__ void wprep_kernel(const float* __restrict__ dw,
                             const float* __restrict__ ow1,
                             const float* __restrict__ fw1,
                             const float* __restrict__ ow2,
                             const float* __restrict__ fw2) {
    int t = blockIdx.x * blockDim.x + threadIdx.x;
    if (t < WP_N1) {
        int o  = t / KDIM;
        int r  = t % KDIM;
        int c  = r / 9;
        int kk = r % 9;
        g_dwt2[(size_t)o * KDIM + kk * 128 + c] = to_tf32(dw[t]);
        return;
    }
    t -= WP_N1;
    if (t < WP_N2) {
        int o  = t / (130 * 9);
        int r  = t % (130 * 9);
        int c  = r / 9;
        int kk = r % 9;
        g_wc1[(kk * 64 + o) * CPAD1 + c] = to_tf32(ow1[t]);
        return;
    }
    t -= WP_N2;
    if (t < WP_N3) {
        int o  = t / (128 * 9);
        int r  = t % (128 * 9);
        int c  = r / 9;
        int kk = r % 9;
        g_wc3[(kk * 64 + o) * CFEAT + c] = to_tf32(fw1[t]);
        return;
    }
    t -= WP_N3;
    if (t < WP_N4) {
        int o  = t / (64 * 9);
        int r  = t % (64 * 9);
        int c  = r / 9;
        int kk = r % 9;
        g_wc2[(kk * 32 + o) * 64 + c] = to_tf32(ow2[t]);
        return;
    }
    t -= WP_N4;
    if (t < WP_N5) {
        int o  = t / (64 * 9);
        int r  = t % (64 * 9);
        int c  = r / 9;
        int kk = r % 9;
        g_wc4[(kk * 32 + o) * 64 + c] = to_tf32(fw2[t]);
    }
}

// ---------------------------------------------------------------------------
// catT: concat(feat[128], flow[2]) NCHW -> g_inT1[b][px][160] (tf32, zero pad)
// ---------------------------------------------------------------------------
__global__ __launch_bounds__(256)
void catT_kernel(const float* __restrict__ feat, const float* __restrict__ flow) {
    __shared__ float s[64][164];
    const int tid = threadIdx.x;
    const int pxt = tid & 63;
    const int cg  = tid >> 6;
    const int b   = blockIdx.z;
    const int px0 = blockIdx.x * 64;
    const int px  = px0 + pxt;

#pragma unroll 8
    for (int j = 0; j < 40; j++) {
        int c = cg * 40 + j;
        float v = 0.f;
        if (c < 128)      v = feat[(size_t)(b * 128 + c) * PLANE + px];
        else if (c < 130) v = flow[(size_t)(b * 2 + (c - 128)) * PLANE + px];
        s[pxt][c] = to_tf32(v);
    }
    __syncthreads();

    const int r = tid >> 2;
    const int q = tid & 3;
    float* dst = g_inT1 + (size_t)(b * PLANE + px0 + r) * CPAD1 + q * 40;
    const float* src = &s[r][q * 40];
#pragma unroll
    for (int i = 0; i < 10; i++)
        ((float4*)dst)[i] = ((const float4*)src)[i];
}

// ---------------------------------------------------------------------------
// conv3x3 via mma.sync tf32 (round-14 tile: 128 px x 64 o, grid (HH,1,B)).
// SINGLE-BARRIER pipeline: wait -> sync -> issue load(ch+1) -> mma(ch).
// Buffer ch+1 (== buf of ch-1) is free: all warps passed sync after mma(ch-1).
// ---------------------------------------------------------------------------
#define CAP 36
#define CONV_AF (128 * CAP)
#define CONV_BF (64 * CAP)
#define CONV_SMEM (2 * (CONV_AF + CONV_BF) * 4)   // 55296 B

template <int CPAD, bool RELU>
__global__ __launch_bounds__(256)
void conv_mma_kernel(const float* __restrict__ inT, const float* __restrict__ wt,
                     const float* __restrict__ bias, float* __restrict__ outT) {
    constexpr int CPC = CPAD / 32;
    constexpr int NCH = 9 * CPC;

    extern __shared__ float dsm[];
    const uint32_t sb = (uint32_t)__cvta_generic_to_shared(dsm);
    const uint32_t As_a[2] = {sb, sb + (CONV_AF + CONV_BF) * 4};
    const uint32_t Bs_a[2] = {sb + CONV_AF * 4,
                              sb + (2 * CONV_AF + CONV_BF) * 4};

    const int tid = threadIdx.x;
    const int lid = tid & 31;
    const int wid = tid >> 5;
    const int h   = blockIdx.x;
    const int b   = blockIdx.z;

    auto load_chunk = [&](int lch, int buf) {
        const int tap = lch / CPC;
        const int c0  = (lch % CPC) * 32;
        const int dh  = tap / 3 - 1;
        const int dw  = tap % 3 - 1;
        const int h2  = h + dh;
        const bool vh = (h2 >= 0) && (h2 < HH);
        const int h2c = vh ? h2 : 0;
        const float* inrow = inT + (size_t)(b * PLANE + h2c * WW) * CPAD;
#pragma unroll
        for (int i = 0; i < 4; i++) {
            int seg = tid * 4 + i;
            int row = seg >> 3;
            int s8  = seg & 7;
            int ws  = row + dw;
            bool v  = vh && (ws >= 0) && (ws < WW);
            int wsc = v ? ws : 0;
            cp16z(As_a[buf] + (uint32_t)(row * CAP + s8 * 4) * 4,
                  inrow + (size_t)wsc * CPAD + c0 + s8 * 4, v ? 16u : 0u);
        }
#pragma unroll
        for (int i = 0; i < 2; i++) {
            int seg = tid * 2 + i;
            int o   = seg >> 3;
            int s8  = seg & 7;
            cp16s(Bs_a[buf] + (uint32_t)(o * CAP + s8 * 4) * 4,
                  wt + (size_t)(tap * 64 + o) * CPAD + c0 + s8 * 4);
        }
        CP_COMMIT();
    };

    const int wm = wid & 3;
    const int wn = wid >> 2;
    const int j = lid >> 3, i8 = lid & 7;
    const uint32_t aoff = (uint32_t)(((j & 1) * 8 + i8) * CAP + (j >> 1) * 4) * 4;
    const uint32_t boff = (uint32_t)(((j >> 1) * 8 + i8) * CAP + (j & 1) * 4) * 4;

    float c[2][4][4];
#pragma unroll
    for (int mt = 0; mt < 2; mt++)
#pragma unroll
        for (int nt = 0; nt < 4; nt++)
#pragma unroll
            for (int e = 0; e < 4; e++) c[mt][nt][e] = 0.f;

    load_chunk(0, 0);

    for (int ch = 0; ch < NCH; ch++) {
        const int cur = ch & 1;
        cp_wait<0>();
        __syncthreads();
        if (ch + 1 < NCH) load_chunk(ch + 1, cur ^ 1);

#pragma unroll
        for (int ks = 0; ks < 4; ks++) {
            const uint32_t kk4 = (uint32_t)(ks * 8) * 4;
            uint32_t a[2][4];
#pragma unroll
            for (int mt = 0; mt < 2; mt++)
                LDMX4(a[mt], As_a[cur] + (uint32_t)((wm * 32 + mt * 16) * CAP) * 4
                             + kk4 + aoff);
            uint32_t bf[2][4];
#pragma unroll
            for (int g = 0; g < 2; g++)
                LDMX4(bf[g], Bs_a[cur] + (uint32_t)((wn * 32 + g * 16) * CAP) * 4
                             + kk4 + boff);
#pragma unroll
            for (int mt = 0; mt < 2; mt++)
#pragma unroll
                for (int nt = 0; nt < 4; nt++)
                    mma_tf32_16n8k8(c[mt][nt], a[mt],
                                    bf[nt >> 1][(nt & 1) * 2],
                                    bf[nt >> 1][(nt & 1) * 2 + 1]);
        }
    }
    __syncthreads();

    // Epilogue: frags (+bias, relu, tf32) -> smem [px][o] (stride 68) -> outT
    float* s_t = dsm;
#pragma unroll
    for (int mt = 0; mt < 2; mt++)
#pragma unroll
        for (int nt = 0; nt < 4; nt++) {
            int px = wm * 32 + mt * 16 + (lid >> 2);
            int o  = wn * 32 + nt * 8 + (lid & 3) * 2;
            float b0 = __ldg(&bias[o]);
            float b1 = __ldg(&bias[o + 1]);
            float v0 = c[mt][nt][0] + b0;
            float v1 = c[mt][nt][1] + b1;
            float v2 = c[mt][nt][2] + b0;
            float v3 = c[mt][nt][3] + b1;
            if (RELU) {
                v0 = fmaxf(v0, 0.f); v1 = fmaxf(v1, 0.f);
                v2 = fmaxf(v2, 0.f); v3 = fmaxf(v3, 0.f);
            }
            s_t[px * 68 + o]           = to_tf32(v0);
            s_t[px * 68 + o + 1]       = to_tf32(v1);
            s_t[(px + 8) * 68 + o]     = to_tf32(v2);
            s_t[(px + 8) * 68 + o + 1] = to_tf32(v3);
        }
    __syncthreads();
    {
        const int px = tid >> 1;
        const int hf = tid & 1;
        float* dst = outT + (size_t)(b * PLANE + h * WW + px) * 64 + hf * 32;
        const float* src = s_t + px * 68 + hf * 32;
#pragma unroll
        for (int i = 0; i < 8; i++)
            ((float4*)dst)[i] = ((const float4*)src)[i];
    }
}

// ---------------------------------------------------------------------------
// Small conv3x3 via mma (single-barrier pipeline). grid = (HH, 1, B).
// ---------------------------------------------------------------------------
#define SC_AF (128 * CAP)
#define SC_BF (32 * CAP)
#define SC_SMEM (2 * (SC_AF + SC_BF) * 4)   // 46080 B

template <int COUT, bool RES>
__global__ __launch_bounds__(256)
void conv_mma_small_kernel(const float* __restrict__ inT, const float* __restrict__ wsm,
                           const float* __restrict__ bias, const float* __restrict__ res,
                           float* __restrict__ out) {
    constexpr int NCH = 18;

    extern __shared__ float dsm[];
    const uint32_t sb = (uint32_t)__cvta_generic_to_shared(dsm);
    const uint32_t As_a[2] = {sb, sb + (SC_AF + SC_BF) * 4};
    const uint32_t Bs_a[2] = {sb + SC_AF * 4, sb + (2 * SC_AF + SC_BF) * 4};

    const int tid = threadIdx.x;
    const int lid = tid & 31;
    const int wid = tid >> 5;
    const int h   = blockIdx.x;
    const int b   = blockIdx.z;

    auto load_chunk = [&](int lch, int buf) {
        const int tap = lch >> 1;
        const int c0  = (lch & 1) * 32;
        const int dh  = tap / 3 - 1;
        const int dw  = tap % 3 - 1;
        const int h2  = h + dh;
        const bool vh = (h2 >= 0) && (h2 < HH);
        const int h2c = vh ? h2 : 0;
        const float* inrow = inT + (size_t)(b * PLANE + h2c * WW) * 64;
#pragma unroll
        for (int i = 0; i < 4; i++) {
            int seg = tid * 4 + i;
            int row = seg >> 3;
            int s8  = seg & 7;
            int ws  = row + dw;
            bool v  = vh && (ws >= 0) && (ws < WW);
            int wsc = v ? ws : 0;
            cp16z(As_a[buf] + (uint32_t)(row * CAP + s8 * 4) * 4,
                  inrow + (size_t)wsc * 64 + c0 + s8 * 4, v ? 16u : 0u);
        }
        {
            int o  = tid >> 3;
            int s8 = tid & 7;
            cp16s(Bs_a[buf] + (uint32_t)(o * CAP + s8 * 4) * 4,
                  wsm + (size_t)(tap * 32 + o) * 64 + c0 + s8 * 4);
        }
        CP_COMMIT();
    };

    const int j = lid >> 3, i8 = lid & 7;
    const uint32_t aoff = (uint32_t)(((j & 1) * 8 + i8) * CAP + (j >> 1) * 4) * 4;
    const uint32_t boff = (uint32_t)(((j >> 1) * 8 + i8) * CAP + (j & 1) * 4) * 4;

    float c[4][4];
#pragma unroll
    for (int nt = 0; nt < 4; nt++)
#pragma unroll
        for (int e = 0; e < 4; e++) c[nt][e] = 0.f;

    load_chunk(0, 0);

    for (int ch = 0; ch < NCH; ch++) {
        const int cur = ch & 1;
        cp_wait<0>();
        __syncthreads();
        if (ch + 1 < NCH) load_chunk(ch + 1, cur ^ 1);

#pragma unroll
        for (int ks = 0; ks < 4; ks++) {
            const uint32_t kk4 = (uint32_t)(ks * 8) * 4;
            uint32_t a[4];
            LDMX4(a, As_a[cur] + (uint32_t)((wid * 16) * CAP) * 4 + kk4 + aoff);
            uint32_t bf[2][4];
#pragma unroll
            for (int g = 0; g < 2; g++)
                LDMX4(bf[g], Bs_a[cur] + (uint32_t)((g * 16) * CAP) * 4 + kk4 + boff);
#pragma unroll
            for (int nt = 0; nt < 4; nt++)
                mma_tf32_16n8k8(c[nt], a,
                                bf[nt >> 1][(nt & 1) * 2],
                                bf[nt >> 1][(nt & 1) * 2 + 1]);
        }
    }
    __syncthreads();

    float* s_t = dsm;
#pragma unroll
    for (int nt = 0; nt < 4; nt++) {
        int px = wid * 16 + (lid >> 2);
        int o  = nt * 8 + (lid & 3) * 2;
        s_t[px * 34 + o]           = c[nt][0];
        s_t[px * 34 + o + 1]       = c[nt][1];
        s_t[(px + 8) * 34 + o]     = c[nt][2];
        s_t[(px + 8) * 34 + o + 1] = c[nt][3];
    }
    __syncthreads();
    for (int idx = tid; idx < COUT * 128; idx += 256) {
        int o  = idx >> 7;
        int px = idx & 127;
        float v = s_t[px * 34 + o] + __ldg(&bias[o]);
        size_t gi = (size_t)(b * COUT + o) * PLANE + h * WW + px;
        if (RES) v += res[gi];
        out[gi] = v;
    }
}

// ---------------------------------------------------------------------------
// FUSED deform GEMM, single-barrier pipeline: gather_A(ch+1) now overlaps
// mma(ch) (it sits between the barrier and the MMA phase). grid = (128,1,B).
// ---------------------------------------------------------------------------
#define AP 36
#define TILE_F (128 * AP)
#define FD_SMEM ((4608 * 2 + 4 * TILE_F) * 4)       // 110592 B

__global__ __launch_bounds__(256)
void dgemm_fused_kernel(const float* __restrict__ feat, const float* __restrict__ offs,
                        const float* __restrict__ dbias) {
    constexpr int NCH = KDIM / 32;

    extern __shared__ float dsm[];
    int*   s_idx = (int*)dsm;
    float* s_wt  = dsm + 4608;
    float* A_f[2] = {dsm + 9216,  dsm + 9216 + TILE_F};
    const uint32_t sb = (uint32_t)__cvta_generic_to_shared(dsm);
    const uint32_t Bs_a[2] = {sb + (9216 + 2 * TILE_F) * 4,
                              sb + (9216 + 3 * TILE_F) * 4};
    const uint32_t As_a[2] = {sb + 9216 * 4, sb + (9216 + TILE_F) * 4};

    const int tid = threadIdx.x;
    const int lid = tid & 31;
    const int wid = tid >> 5;
    const int px0 = blockIdx.x * 128;
    const int b   = blockIdx.z;

    auto load_B = [&](int ch, int buf) {
        const int kc0 = (ch >> 2) * 128 + (ch & 3) * 32;
#pragma unroll
        for (int i = 0; i < 4; i++) {
            int seg = tid * 4 + i;
            int o   = seg >> 3;
            int s   = seg & 7;
            cp16s(Bs_a[buf] + (uint32_t)(o * AP + s * 4) * 4,
                  g_dwt2 + (size_t)o * KDIM + kc0 + s * 4);
        }
        CP_COMMIT();
    };

    load_B(0, 0);

    for (int t = tid; t < 1152; t += 256) {
        int px = t / 9;
        int k  = t % 9;
        int g  = px0 + px;
        int h  = g >> 7;
        int w  = g & 127;
        float offy = offs[(size_t)(b * 18 + 2 * k)     * PLANE + g];
        float offx = offs[(size_t)(b * 18 + 2 * k + 1) * PLANE + g];
        float fy = (float)(h + k / 3 - 1) + offy;
        float fx = (float)(w + k % 3 - 1) + offx;
        float y0f = floorf(fy), x0f = floorf(fx);
        float ly = fy - y0f, lx = fx - x0f;
        int y0 = (int)y0f, x0 = (int)x0f;
        float q[4] = {(1.f - ly) * (1.f - lx), (1.f - ly) * lx,
                      ly * (1.f - lx),          ly * lx};
        int ys[4] = {y0, y0, y0 + 1, y0 + 1};
        int xs[4] = {x0, x0 + 1, x0, x0 + 1};
#pragma unroll
        for (int c4 = 0; c4 < 4; c4++) {
            bool valid = (ys[c4] >= 0) && (ys[c4] < HH) && (xs[c4] >= 0) && (xs[c4] < WW);
            s_idx[t * 4 + c4] = valid ? (ys[c4] * WW + xs[c4]) : 0;
            s_wt [t * 4 + c4] = valid ? q[c4] : 0.f;
        }
    }
    __syncthreads();

    const int gpx = tid & 127;
    const int gcg = tid >> 7;
    auto gather_A = [&](int ch, int buf) {
        const int k  = ch >> 2;
        const int c0 = (ch & 3) * 32 + gcg * 16;
        const int4   iv = *(const int4*)&s_idx[(gpx * 9 + k) * 4];
        const float4 qv = *(const float4*)&s_wt[(gpx * 9 + k) * 4];
        const float* fb = feat + (size_t)b * CFEAT * PLANE;
        float* arow = A_f[buf] + gpx * AP + gcg * 16;
#pragma unroll
        for (int j = 0; j < 16; j++) {
            const float* fc = fb + (size_t)(c0 + j) * PLANE;
            arow[j] = to_tf32(qv.x * fc[iv.x] + qv.y * fc[iv.y]
                            + qv.z * fc[iv.z] + qv.w * fc[iv.w]);
        }
    };

    gather_A(0, 0);

    const int wpx = wid & 1;
    const int wo  = wid >> 1;
    const int j = lid >> 3, i8 = lid & 7;
    const uint32_t aoff = (uint32_t)(((j & 1) * 8 + i8) * AP + (j >> 1) * 4) * 4;
    const uint32_t boff = (uint32_t)(((j >> 1) * 8 + i8) * AP + (j & 1) * 4) * 4;

    float c[4][4][4];
#pragma unroll
    for (int mt = 0; mt < 4; mt++)
#pragma unroll
        for (int nt = 0; nt < 4; nt++)
#pragma unroll
            for (int e = 0; e < 4; e++) c[mt][nt][e] = 0.f;

    for (int ch = 0; ch < NCH; ch++) {
        const int cur = ch & 1;
        cp_wait<0>();
        __syncthreads();
        if (ch + 1 < NCH) {
            load_B(ch + 1, cur ^ 1);
            gather_A(ch + 1, cur ^ 1);   // overlaps the MMA phase below
        }

#pragma unroll
        for (int ks = 0; ks < 4; ks++) {
            const uint32_t kk4 = (uint32_t)(ks * 8) * 4;
            uint32_t a[4][4];
#pragma unroll
            for (int mt = 0; mt < 4; mt++)
                LDMX4(a[mt], As_a[cur] + (uint32_t)((wpx * 64 + mt * 16) * AP) * 4
                             + kk4 + aoff);
            uint32_t bf[2][4];
#pragma unroll
            for (int g = 0; g < 2; g++)
                LDMX4(bf[g], Bs_a[cur] + (uint32_t)((wo * 32 + g * 16) * AP) * 4
                             + kk4 + boff);
#pragma unroll
            for (int mt = 0; mt < 4; mt++)
#pragma unroll
                for (int nt = 0; nt < 4; nt++)
                    mma_tf32_16n8k8(c[mt][nt], a[mt],
                                    bf[nt >> 1][(nt & 1) * 2],
                                    bf[nt >> 1][(nt & 1) * 2 + 1]);
        }
    }
    __syncthreads();

    float* s_t = dsm;
#pragma unroll
    for (int mt = 0; mt < 4; mt++)
#pragma unroll
        for (int nt = 0; nt < 4; nt++) {
            int pxb = wpx * 64 + mt * 16 + (lid >> 2);
            int ob  = wo * 32 + nt * 8 + (lid & 3) * 2;
            float b0 = __ldg(&dbias[ob]);
            float b1 = __ldg(&dbias[ob + 1]);
            s_t[pxb * 132 + ob]           = to_tf32(c[mt][nt][0] + b0);
            s_t[pxb * 132 + ob + 1]       = to_tf32(c[mt][nt][1] + b1);
            s_t[(pxb + 8) * 132 + ob]     = to_tf32(c[mt][nt][2] + b0);
            s_t[(pxb + 8) * 132 + ob + 1] = to_tf32(c[mt][nt][3] + b1);
        }
    __syncthreads();
    {
        const int px = tid >> 1;
        const int hf = tid & 1;
        float* dst = g_tmp2T + (size_t)(b * PLANE + px0 + px) * CFEAT + hf * 64;
        const float* src = s_t + px * 132 + hf * 64;
#pragma unroll
        for (int i = 0; i < 16; i++)
            ((float4*)dst)[i] = ((const float4*)src)[i];
    }
}

// ---------------------------------------------------------------------------
// Launch
// ---------------------------------------------------------------------------
extern "C" void kernel_launch(void* const* d_in, const int* in_sizes, int n_in,
                              void* d_out, int out_size) {
    const float* feat    = (const float*)d_in[0];
    const float* flow    = (const float*)d_in[1];
    const float* off_w1  = (const float*)d_in[2];
    const float* off_b1  = (const float*)d_in[3];
    const float* off_w2  = (const float*)d_in[4];
    const float* off_b2  = (const float*)d_in[5];
    const float* dweight = (const float*)d_in[6];
    const float* dbias   = (const float*)d_in[7];
    const float* fh_w1   = (const float*)d_in[8];
    const float* fh_b1   = (const float*)d_in[9];
    const float* fh_w2   = (const float*)d_in[10];
    const float* fh_b2   = (const float*)d_in[11];
    float* out = (float*)d_out;

    float *tmp1T, *off, *tmp2T, *tmp3T, *wc1, *wc3, *wc2, *wc4, *inT1;
    cudaGetSymbolAddress((void**)&tmp1T, g_tmp1T);
    cudaGetSymbolAddress((void**)&off,   g_off);
    cudaGetSymbolAddress((void**)&tmp2T, g_tmp2T);
    cudaGetSymbolAddress((void**)&tmp3T, g_tmp3T);
    cudaGetSymbolAddress((void**)&wc1,   g_wc1);
    cudaGetSymbolAddress((void**)&wc3,   g_wc3);
    cudaGetSymbolAddress((void**)&wc2,   g_wc2);
    cudaGetSymbolAddress((void**)&wc4,   g_wc4);
    cudaGetSymbolAddress((void**)&inT1,  g_inT1);

    cudaFuncSetAttribute(dgemm_fused_kernel,
                         cudaFuncAttributeMaxDynamicSharedMemorySize, FD_SMEM);
    cudaFuncSetAttribute(conv_mma_kernel<CPAD1, true>,
                         cudaFuncAttributeMaxDynamicSharedMemorySize, CONV_SMEM);
    cudaFuncSetAttribute(conv_mma_kernel<CFEAT, true>,
                         cudaFuncAttributeMaxDynamicSharedMemorySize, CONV_SMEM);
    cudaFuncSetAttribute(conv_mma_small_kernel<18, false>,
                         cudaFuncAttributeMaxDynamicSharedMemorySize, SC_SMEM);
    cudaFuncSetAttribute(conv_mma_small_kernel<2, true>,
                         cudaFuncAttributeMaxDynamicSharedMemorySize, SC_SMEM);

    // 0. all weight transposes (one launch)
    wprep_kernel<<<(WP_TOTAL + 255) / 256, 256>>>(dweight, off_w1, fh_w1,
                                                  off_w2, fh_w2);

    // 1a. transpose concat(feat, flow) -> inT1 [px][160]
    catT_kernel<<<dim3(PLANE / 64, 1, BATCH), 256>>>(feat, flow);

    // 1b. conv1 via mma: 130 -> 64, relu -> tmp1T
    conv_mma_kernel<CPAD1, true><<<dim3(HH, 1, BATCH), 256, CONV_SMEM>>>(
        inT1, wc1, off_b1, tmp1T);

    // 2. conv2 via mma: 64 -> 18 -> offsets NCHW
    conv_mma_small_kernel<18, false><<<dim3(HH, 1, BATCH), 256, SC_SMEM>>>(
        tmp1T, wc2, off_b2, nullptr, off);

    // 3. FUSED gather + deform GEMM -> tmp2T [px][o] (tf32, +bias)
    dgemm_fused_kernel<<<dim3(128, 1, BATCH), 256, FD_SMEM>>>(feat, off, dbias);

    // 4. fh conv1 via mma: 128 -> 64, relu -> tmp3T
    conv_mma_kernel<CFEAT, true><<<dim3(HH, 1, BATCH), 256, CONV_SMEM>>>(
        tmp2T, wc3, fh_b1, tmp3T);

    // 5. fh conv2 via mma: 64 -> 2, + flow residual -> out NCHW
    conv_mma_small_kernel<2, true><<<dim3(HH, 1, BATCH), 256, SC_SMEM>>>(
        tmp3T, wc4, fh_b2, flow, out);
}